// round 2
// baseline (speedup 1.0000x reference)
#include <cuda_runtime.h>
#include <math.h>

#define BB 4
#define CIN 64
#define HH 128
#define WW 128
#define HWSZ (HH*WW)
#define COUT 64
#define C27 27
#define CK 576  // CIN*9

// Scratch (device globals: no allocation allowed in kernel_launch)
__device__ __align__(16) float g_om[BB*C27*HWSZ];   // dy(0..8), dx(9..17), sigmoid(mask)(18..26)
__device__ __align__(16) float g_wT[CK*COUT];       // main weight: [k][c][64]
__device__ __align__(16) float g_owT[CK*28];        // offset weight: [c*9+k][28]

typedef unsigned long long u64;

__device__ __forceinline__ u64 pack2(float a, float b) {
    u64 r;
    asm("mov.b64 %0, {%1, %2};" : "=l"(r) : "f"(a), "f"(b));
    return r;
}
__device__ __forceinline__ void unpack2(u64 v, float& a, float& b) {
    asm("mov.b64 {%0, %1}, %2;" : "=f"(a), "=f"(b) : "l"(v));
}
__device__ __forceinline__ void ffma2(u64& d, u64 a, u64 b) {
    asm("fma.rn.f32x2 %0, %1, %2, %0;" : "+l"(d) : "l"(a), "l"(b));
}

// ---------------------------------------------------------------------------
// Kernel 0: weight transposes
// ---------------------------------------------------------------------------
__global__ void prep_kernel(const float* __restrict__ wt, const float* __restrict__ owt) {
    int idx = blockIdx.x * blockDim.x + threadIdx.x;
    if (idx < CK*COUT) {
        // dest layout [k][c][o]
        int o = idx & 63;
        int kc = idx >> 6;
        int k = kc / CIN;
        int c = kc - k * CIN;
        g_wT[idx] = wt[o*CK + c*9 + k];
    }
    if (idx < CK*28) {
        int o  = idx % 28;
        int ck = idx / 28;   // c*9+k
        g_owT[idx] = (o < C27) ? owt[o*CK + ck] : 0.f;
    }
}

// ---------------------------------------------------------------------------
// Kernel 1: offset/mask conv (3x3 pad1), 27 out ch. P=2 pixels/thread, FFMA2.
// ---------------------------------------------------------------------------
__global__ __launch_bounds__(128) void offset_kernel(const float* __restrict__ x,
                                                     const float* __restrict__ ob) {
    int t = blockIdx.x * 128 + threadIdx.x;
    int warp = t >> 5, lane = t & 31;
    int p0 = warp * 64 + lane;     // warp covers 64 consecutive pixels
    int b  = p0 >> 14;
    int hwA = p0 & (HWSZ - 1);
    int hwB = hwA + 32;

    // packed accumulators: 14 x f32x2 per pixel (channels 2q, 2q+1)
    u64 accA[14], accB[14];
    #pragma unroll
    for (int q = 0; q < 14; q++) {
        float b0 = __ldg(ob + 2*q);
        float b1 = (2*q + 1 < C27) ? __ldg(ob + 2*q + 1) : 0.f;
        accA[q] = pack2(b0, b1);
        accB[q] = accA[q];
    }

    // neighbor indices with -1 sentinel (pixel-invariant over c)
    int nA[9], nB[9];
    {
        int hA = hwA >> 7, wA = hwA & 127;
        int hB = hwB >> 7, wB = hwB & 127;
        #pragma unroll
        for (int kh = 0; kh < 3; kh++)
            #pragma unroll
            for (int kw = 0; kw < 3; kw++) {
                int k = kh*3 + kw;
                int h1 = hA - 1 + kh, w1 = wA - 1 + kw;
                nA[k] = (h1 >= 0 && h1 < HH && w1 >= 0 && w1 < WW) ? h1*WW + w1 : -1;
                int h2 = hB - 1 + kh, w2 = wB - 1 + kw;
                nB[k] = (h2 >= 0 && h2 < HH && w2 >= 0 && w2 < WW) ? h2*WW + w2 : -1;
            }
    }

    const float* xb = x + (size_t)b * CIN * HWSZ;
    #pragma unroll 1
    for (int c = 0; c < CIN; c++) {
        const float* xc = xb + c * HWSZ;
        float xvA[9], xvB[9];
        #pragma unroll
        for (int k = 0; k < 9; k++) {
            xvA[k] = (nA[k] >= 0) ? __ldg(xc + nA[k]) : 0.f;
            xvB[k] = (nB[k] >= 0) ? __ldg(xc + nB[k]) : 0.f;
        }
        const u64* wrow = (const u64*)(g_owT + c * 9 * 28);
        #pragma unroll
        for (int k = 0; k < 9; k++) {
            u64 vA = pack2(xvA[k], xvA[k]);
            u64 vB = pack2(xvB[k], xvB[k]);
            const ulonglong2* wp = (const ulonglong2*)(wrow + k * 14);
            #pragma unroll
            for (int q = 0; q < 7; q++) {
                ulonglong2 ww = __ldg(wp + q);
                ffma2(accA[2*q],   vA, ww.x);
                ffma2(accA[2*q+1], vA, ww.y);
                ffma2(accB[2*q],   vB, ww.x);
                ffma2(accB[2*q+1], vB, ww.y);
            }
        }
    }

    float* omA = g_om + (size_t)b * C27 * HWSZ + hwA;
    float* omB = omA + 32;
    #pragma unroll
    for (int q = 0; q < 14; q++) {
        float a0, a1, c0, c1;
        unpack2(accA[q], a0, a1);
        unpack2(accB[q], c0, c1);
        int o0 = 2*q, o1 = 2*q + 1;
        if (o0 >= 18) a0 = 1.f / (1.f + __expf(-a0));
        if (o0 >= 18) c0 = 1.f / (1.f + __expf(-c0));
        omA[o0*HWSZ] = a0;
        omB[o0*HWSZ] = c0;
        if (o1 < C27) {
            if (o1 >= 18) a1 = 1.f / (1.f + __expf(-a1));
            if (o1 >= 18) c1 = 1.f / (1.f + __expf(-c1));
            omA[o1*HWSZ] = a1;
            omB[o1*HWSZ] = c1;
        }
    }
}

// ---------------------------------------------------------------------------
// Kernel 2: deformable sampling + implicit GEMM. P=2 pixels/thread, FFMA2.
// Per (c,k): 8 gather LDG + 16 weight LDG.128 + 64 FFMA2 (serves 2 pixels
// x 64 out channels).
// ---------------------------------------------------------------------------
__global__ __launch_bounds__(128) void dcn_kernel(const float* __restrict__ x,
                                                  const float* __restrict__ bias,
                                                  float* __restrict__ out) {
    int t = blockIdx.x * 128 + threadIdx.x;
    int warp = t >> 5, lane = t & 31;
    int p0 = warp * 64 + lane;
    int b  = p0 >> 14;
    int hwA = p0 & (HWSZ - 1);
    int hwB = hwA + 32;
    int hA = hwA >> 7, wA = hwA & 127;
    int hB = hwB >> 7, wB = hwB & 127;

    u64 accA[32], accB[32];
    #pragma unroll
    for (int q = 0; q < 16; q++) {
        ulonglong2 bb = __ldg((const ulonglong2*)bias + q);
        accA[2*q]   = bb.x;  accA[2*q+1] = bb.y;
        accB[2*q]   = bb.x;  accB[2*q+1] = bb.y;
    }

    const float* xb  = x + (size_t)b * CIN * HWSZ;
    const float* omA = g_om + (size_t)b * C27 * HWSZ + hwA;
    const float* omB = omA + 32;

    #pragma unroll 1
    for (int k = 0; k < 9; k++) {
        int kh = k / 3, kw = k - kh*3;
        // bilinear params for both pixels (channel-independent)
        int iA00, iA01, iA10, iA11, iB00, iB01, iB10, iB11;
        float wA00, wA01, wA10, wA11, wB00, wB01, wB10, wB11;
        {
            float dy = __ldg(omA + k*HWSZ);
            float dx = __ldg(omA + (9+k)*HWSZ);
            float m  = __ldg(omA + (18+k)*HWSZ);
            float hh = (float)(hA - 1 + kh) + dy;
            float ww = (float)(wA - 1 + kw) + dx;
            float h0f = floorf(hh), w0f = floorf(ww);
            float lh = hh - h0f, lw = ww - w0f;
            int h0 = (int)h0f, w0 = (int)w0f, h1 = h0+1, w1 = w0+1;
            bool vh0 = (h0>=0)&&(h0<HH), vh1 = (h1>=0)&&(h1<HH);
            bool vw0 = (w0>=0)&&(w0<WW), vw1 = (w1>=0)&&(w1<WW);
            int ch0 = min(max(h0,0),HH-1), ch1 = min(max(h1,0),HH-1);
            int cw0 = min(max(w0,0),WW-1), cw1 = min(max(w1,0),WW-1);
            iA00 = ch0*WW+cw0; iA01 = ch0*WW+cw1; iA10 = ch1*WW+cw0; iA11 = ch1*WW+cw1;
            wA00 = (1.f-lh)*(1.f-lw)*m*((vh0&&vw0)?1.f:0.f);
            wA01 = (1.f-lh)*lw      *m*((vh0&&vw1)?1.f:0.f);
            wA10 = lh*(1.f-lw)      *m*((vh1&&vw0)?1.f:0.f);
            wA11 = lh*lw            *m*((vh1&&vw1)?1.f:0.f);
        }
        {
            float dy = __ldg(omB + k*HWSZ);
            float dx = __ldg(omB + (9+k)*HWSZ);
            float m  = __ldg(omB + (18+k)*HWSZ);
            float hh = (float)(hB - 1 + kh) + dy;
            float ww = (float)(wB - 1 + kw) + dx;
            float h0f = floorf(hh), w0f = floorf(ww);
            float lh = hh - h0f, lw = ww - w0f;
            int h0 = (int)h0f, w0 = (int)w0f, h1 = h0+1, w1 = w0+1;
            bool vh0 = (h0>=0)&&(h0<HH), vh1 = (h1>=0)&&(h1<HH);
            bool vw0 = (w0>=0)&&(w0<WW), vw1 = (w1>=0)&&(w1<WW);
            int ch0 = min(max(h0,0),HH-1), ch1 = min(max(h1,0),HH-1);
            int cw0 = min(max(w0,0),WW-1), cw1 = min(max(w1,0),WW-1);
            iB00 = ch0*WW+cw0; iB01 = ch0*WW+cw1; iB10 = ch1*WW+cw0; iB11 = ch1*WW+cw1;
            wB00 = (1.f-lh)*(1.f-lw)*m*((vh0&&vw0)?1.f:0.f);
            wB01 = (1.f-lh)*lw      *m*((vh0&&vw1)?1.f:0.f);
            wB10 = lh*(1.f-lw)      *m*((vh1&&vw0)?1.f:0.f);
            wB11 = lh*lw            *m*((vh1&&vw1)?1.f:0.f);
        }

        const float* xc = xb;
        const ulonglong2* wp = (const ulonglong2*)(g_wT + k * CIN * COUT);
        #pragma unroll 1
        for (int c = 0; c < CIN; c++) {
            float valA = wA00 * __ldg(xc + iA00);
            valA = fmaf(wA01, __ldg(xc + iA01), valA);
            valA = fmaf(wA10, __ldg(xc + iA10), valA);
            valA = fmaf(wA11, __ldg(xc + iA11), valA);
            float valB = wB00 * __ldg(xc + iB00);
            valB = fmaf(wB01, __ldg(xc + iB01), valB);
            valB = fmaf(wB10, __ldg(xc + iB10), valB);
            valB = fmaf(wB11, __ldg(xc + iB11), valB);
            u64 vA = pack2(valA, valA);
            u64 vB = pack2(valB, valB);
            #pragma unroll
            for (int q = 0; q < 16; q++) {
                ulonglong2 ww = __ldg(wp + q);
                ffma2(accA[2*q],   vA, ww.x);
                ffma2(accA[2*q+1], vA, ww.y);
                ffma2(accB[2*q],   vB, ww.x);
                ffma2(accB[2*q+1], vB, ww.y);
            }
            xc += HWSZ;
            wp += 16;
        }
    }

    float* oA = out + (size_t)b * COUT * HWSZ + hwA;
    float* oB = oA + 32;
    #pragma unroll
    for (int q = 0; q < 32; q++) {
        float a0, a1, b0, b1;
        unpack2(accA[q], a0, a1);
        unpack2(accB[q], b0, b1);
        oA[(2*q)*HWSZ]   = a0;
        oA[(2*q+1)*HWSZ] = a1;
        oB[(2*q)*HWSZ]   = b0;
        oB[(2*q+1)*HWSZ] = b1;
    }
}

// ---------------------------------------------------------------------------
extern "C" void kernel_launch(void* const* d_in, const int* in_sizes, int n_in,
                              void* d_out, int out_size) {
    const float* x    = (const float*)d_in[0];  // [4,64,128,128]
    const float* wt   = (const float*)d_in[1];  // [64,64,3,3]
    const float* bias = (const float*)d_in[2];  // [64]
    const float* owt  = (const float*)d_in[3];  // [27,64,3,3]
    const float* ob   = (const float*)d_in[4];  // [27]
    float* out = (float*)d_out;                 // [4,64,128,128]

    prep_kernel<<<(CK*COUT + 255) / 256, 256>>>(wt, owt);
    offset_kernel<<<BB*HWSZ/256, 128>>>(x, ob);
    dcn_kernel<<<BB*HWSZ/256, 128>>>(x, bias, out);
}

// round 3
// speedup vs baseline: 4.6990x; 4.6990x over previous
#include <cuda_runtime.h>
#include <math.h>

#define BB 4
#define CIN 64
#define HH 128
#define WW 128
#define HWSZ (HH*WW)
#define COUT 64
#define C27 27
#define CK 576  // CIN*9

// Scratch (device globals: no allocation allowed in kernel_launch)
__device__ __align__(16) float g_om[BB*C27*HWSZ];   // dy(0..8), dx(9..17), sigmoid(mask)(18..26)
__device__ __align__(16) float g_wT[CK*COUT];       // main weight: [k][c][64]
__device__ __align__(16) float g_owT[CK*28];        // offset weight: [c*9+k][28]

typedef unsigned long long u64;

__device__ __forceinline__ u64 pack2(float a, float b) {
    u64 r;
    asm("mov.b64 %0, {%1, %2};" : "=l"(r) : "f"(a), "f"(b));
    return r;
}
__device__ __forceinline__ void unpack2(u64 v, float& a, float& b) {
    asm("mov.b64 {%0, %1}, %2;" : "=f"(a), "=f"(b) : "l"(v));
}
__device__ __forceinline__ void ffma2(u64& d, u64 a, u64 b) {
    asm("fma.rn.f32x2 %0, %1, %2, %0;" : "+l"(d) : "l"(a), "l"(b));
}

// ---------------------------------------------------------------------------
// Kernel 0: weight transposes
// ---------------------------------------------------------------------------
__global__ void prep_kernel(const float* __restrict__ wt, const float* __restrict__ owt) {
    int idx = blockIdx.x * blockDim.x + threadIdx.x;
    if (idx < CK*COUT) {
        // dest layout [k][c][o]
        int o = idx & 63;
        int kc = idx >> 6;
        int k = kc / CIN;
        int c = kc - k * CIN;
        g_wT[idx] = wt[o*CK + c*9 + k];
    }
    if (idx < CK*28) {
        int o  = idx % 28;
        int ck = idx / 28;   // c*9+k
        g_owT[idx] = (o < C27) ? owt[o*CK + ck] : 0.f;
    }
}

// ---------------------------------------------------------------------------
// Kernel 1: offset/mask conv (3x3 pad1), 27 out ch. 1 px/thread, FFMA2,
// full offset-weight table staged in shared memory (63 KB).
// ---------------------------------------------------------------------------
__global__ __launch_bounds__(256) void offset_kernel(const float* __restrict__ x,
                                                     const float* __restrict__ ob) {
    __shared__ __align__(16) float sow[CK*28];   // 64512 B

    // cooperative stage: 4032 float4
    {
        const float4* src = (const float4*)g_owT;
        float4* dst = (float4*)sow;
        #pragma unroll 4
        for (int i = threadIdx.x; i < CK*28/4; i += 256) dst[i] = __ldg(src + i);
    }
    __syncthreads();

    int t  = blockIdx.x * 256 + threadIdx.x;
    int b  = t >> 14;
    int hw = t & (HWSZ - 1);
    int h  = hw >> 7;
    int w  = hw & 127;

    // packed accumulators: 14 x f32x2 (channels 2q, 2q+1)
    u64 acc[14];
    #pragma unroll
    for (int q = 0; q < 14; q++) {
        float b0 = __ldg(ob + 2*q);
        float b1 = (2*q + 1 < C27) ? __ldg(ob + 2*q + 1) : 0.f;
        acc[q] = pack2(b0, b1);
    }

    // neighbor indices with -1 sentinel (pixel-invariant over c)
    int nidx[9];
    #pragma unroll
    for (int kh = 0; kh < 3; kh++)
        #pragma unroll
        for (int kw = 0; kw < 3; kw++) {
            int hh = h - 1 + kh, ww = w - 1 + kw;
            nidx[kh*3+kw] = (hh >= 0 && hh < HH && ww >= 0 && ww < WW) ? hh*WW + ww : -1;
        }

    const float* xb = x + (size_t)b * CIN * HWSZ;
    #pragma unroll 1
    for (int c = 0; c < CIN; c++) {
        const float* xc = xb + c * HWSZ;
        float xv[9];
        #pragma unroll
        for (int k = 0; k < 9; k++) xv[k] = (nidx[k] >= 0) ? __ldg(xc + nidx[k]) : 0.f;
        #pragma unroll
        for (int k = 0; k < 9; k++) {
            u64 v = pack2(xv[k], xv[k]);
            const ulonglong2* wp = (const ulonglong2*)(sow + (c*9 + k) * 28);
            #pragma unroll
            for (int q = 0; q < 7; q++) {
                ulonglong2 ww = wp[q];
                ffma2(acc[2*q],   v, ww.x);
                ffma2(acc[2*q+1], v, ww.y);
            }
        }
    }

    float* om = g_om + (size_t)b * C27 * HWSZ + hw;
    #pragma unroll
    for (int q = 0; q < 14; q++) {
        float a0, a1;
        unpack2(acc[q], a0, a1);
        int o0 = 2*q, o1 = 2*q + 1;
        if (o0 >= 18) a0 = 1.f / (1.f + __expf(-a0));
        om[o0*HWSZ] = a0;
        if (o1 < C27) {
            if (o1 >= 18) a1 = 1.f / (1.f + __expf(-a1));
            om[o1*HWSZ] = a1;
        }
    }
}

// ---------------------------------------------------------------------------
// Kernel 2: deformable sampling + implicit GEMM. 1 px/thread, FFMA2,
// per-k 16 KB weight tile staged in smem, gathers prefetched one c ahead.
// ---------------------------------------------------------------------------
__global__ __launch_bounds__(256) void dcn_kernel(const float* __restrict__ x,
                                                  const float* __restrict__ bias,
                                                  float* __restrict__ out) {
    __shared__ __align__(16) float sw[CIN*COUT];   // 16 KB, current k

    int t  = blockIdx.x * 256 + threadIdx.x;
    int b  = t >> 14;
    int hw = t & (HWSZ - 1);
    int h  = hw >> 7;
    int w  = hw & 127;

    u64 acc[32];
    #pragma unroll
    for (int q = 0; q < 16; q++) {
        ulonglong2 bb = __ldg((const ulonglong2*)bias + q);
        acc[2*q] = bb.x;  acc[2*q+1] = bb.y;
    }

    const float* xb  = x + (size_t)b * CIN * HWSZ;
    const float* omb = g_om + (size_t)b * C27 * HWSZ + hw;

    #pragma unroll 1
    for (int k = 0; k < 9; k++) {
        // stage this k's weight tile [c][64]
        __syncthreads();
        {
            const float4* src = (const float4*)(g_wT + k * CIN * COUT);
            float4* dst = (float4*)sw;
            #pragma unroll
            for (int i = threadIdx.x; i < CIN*COUT/4; i += 256) dst[i] = __ldg(src + i);
        }
        __syncthreads();

        int kh = k / 3, kw = k - kh*3;
        float dy = __ldg(omb + k*HWSZ);
        float dx = __ldg(omb + (9+k)*HWSZ);
        float m  = __ldg(omb + (18+k)*HWSZ);
        float hh = (float)(h - 1 + kh) + dy;
        float ww = (float)(w - 1 + kw) + dx;
        float h0f = floorf(hh), w0f = floorf(ww);
        float lh = hh - h0f, lw = ww - w0f;
        int h0 = (int)h0f, w0 = (int)w0f, h1 = h0+1, w1 = w0+1;
        bool vh0 = (h0>=0)&&(h0<HH), vh1 = (h1>=0)&&(h1<HH);
        bool vw0 = (w0>=0)&&(w0<WW), vw1 = (w1>=0)&&(w1<WW);
        int ch0 = min(max(h0,0),HH-1), ch1 = min(max(h1,0),HH-1);
        int cw0 = min(max(w0,0),WW-1), cw1 = min(max(w1,0),WW-1);
        int i00 = ch0*WW+cw0, i01 = ch0*WW+cw1;
        int i10 = ch1*WW+cw0, i11 = ch1*WW+cw1;
        float w00 = (1.f-lh)*(1.f-lw)*m*((vh0&&vw0)?1.f:0.f);
        float w01 = (1.f-lh)*lw      *m*((vh0&&vw1)?1.f:0.f);
        float w10 = lh*(1.f-lw)      *m*((vh1&&vw0)?1.f:0.f);
        float w11 = lh*lw            *m*((vh1&&vw1)?1.f:0.f);

        // prefetch c=0 gathers
        float v00 = __ldg(xb + i00), v01 = __ldg(xb + i01);
        float v10 = __ldg(xb + i10), v11 = __ldg(xb + i11);

        const float* xc = xb;
        #pragma unroll 1
        for (int c = 0; c < CIN; c++) {
            float n00, n01, n10, n11;
            if (c < CIN-1) {
                const float* xn = xc + HWSZ;
                n00 = __ldg(xn + i00); n01 = __ldg(xn + i01);
                n10 = __ldg(xn + i10); n11 = __ldg(xn + i11);
            }
            float val = w00 * v00;
            val = fmaf(w01, v01, val);
            val = fmaf(w10, v10, val);
            val = fmaf(w11, v11, val);
            u64 v = pack2(val, val);
            const ulonglong2* wp = (const ulonglong2*)(sw + c * COUT);
            #pragma unroll
            for (int q = 0; q < 16; q++) {
                ulonglong2 wv = wp[q];
                ffma2(acc[2*q],   v, wv.x);
                ffma2(acc[2*q+1], v, wv.y);
            }
            v00 = n00; v01 = n01; v10 = n10; v11 = n11;
            xc += HWSZ;
        }
    }

    float* ob = out + (size_t)b * COUT * HWSZ + hw;
    #pragma unroll
    for (int q = 0; q < 32; q++) {
        float a0, a1;
        unpack2(acc[q], a0, a1);
        ob[(2*q)*HWSZ]   = a0;
        ob[(2*q+1)*HWSZ] = a1;
    }
}

// ---------------------------------------------------------------------------
extern "C" void kernel_launch(void* const* d_in, const int* in_sizes, int n_in,
                              void* d_out, int out_size) {
    const float* x    = (const float*)d_in[0];  // [4,64,128,128]
    const float* wt   = (const float*)d_in[1];  // [64,64,3,3]
    const float* bias = (const float*)d_in[2];  // [64]
    const float* owt  = (const float*)d_in[3];  // [27,64,3,3]
    const float* ob   = (const float*)d_in[4];  // [27]
    float* out = (float*)d_out;                 // [4,64,128,128]

    prep_kernel<<<(CK*COUT + 255) / 256, 256>>>(wt, owt);
    offset_kernel<<<BB*HWSZ/256, 256>>>(x, ob);
    dcn_kernel<<<BB*HWSZ/256, 256>>>(x, bias, out);
}